// round 5
// baseline (speedup 1.0000x reference)
#include <cuda_runtime.h>
#include <math.h>

#define N_NODES 50000
#define H 8
#define D 32
#define DEG 16
#define HD (H * D)            // 256
#define NH (N_NODES * H)

// Scratch for precomputed attention dot-products (no cudaMalloc allowed).
__device__ float g_el[NH];
__device__ float g_er[NH];

__device__ __forceinline__ float dot4(float4 a, float4 b) {
    return a.x * b.x + a.y * b.y + a.z * b.z + a.w * b.w;
}

// ---------------------------------------------------------------------------
// Kernel 1: one warp per node, fully coalesced (unchanged, ~9us).
// ---------------------------------------------------------------------------
__global__ __launch_bounds__(256) void precompute_dots(
        const float* __restrict__ feat,
        const float* __restrict__ attn_l,
        const float* __restrict__ attn_r) {
    const int gw   = (blockIdx.x * blockDim.x + threadIdx.x) >> 5;  // node
    const int lane = threadIdx.x & 31;
    if (gw >= N_NODES) return;

    const float4* f4 = reinterpret_cast<const float4*>(feat) + (size_t)gw * 64;
    const float4* al = reinterpret_cast<const float4*>(attn_l);
    const float4* ar = reinterpret_cast<const float4*>(attn_r);

    const float4 f0 = f4[lane];
    const float4 f1 = f4[lane + 32];
    const float4 a0 = al[lane], a1 = al[lane + 32];
    const float4 b0 = ar[lane], b1 = ar[lane + 32];

    float pl0 = dot4(f0, a0);
    float pl1 = dot4(f1, a1);
    float pr0 = dot4(f0, b0);
    float pr1 = dot4(f1, b1);

#pragma unroll
    for (int m = 4; m >= 1; m >>= 1) {
        pl0 += __shfl_xor_sync(0xffffffffu, pl0, m);
        pl1 += __shfl_xor_sync(0xffffffffu, pl1, m);
        pr0 += __shfl_xor_sync(0xffffffffu, pr0, m);
        pr1 += __shfl_xor_sync(0xffffffffu, pr1, m);
    }

    const int g    = lane >> 3;
    const int lo   = lane & 7;
    const int base = gw * H;
    if      (lo == 0) g_el[base + g]     = pl0;
    else if (lo == 1) g_el[base + g + 4] = pl1;
    else if (lo == 2) g_er[base + g]     = pr0;
    else if (lo == 3) g_er[base + g + 4] = pr1;
}

// ---------------------------------------------------------------------------
// Kernel 2: ONE WARP PER NODE, barrier-free, zero smem.
// Lane (h = lane>>2, q = lane&3) owns 8 floats of the 256-float row:
//   off0 = h*32 + q*8  (float4),  off1 = off0 + 4  (float4)
// Per edge the warp loads 1KB contiguous (2x LDG.128/lane).
// Softmax: lane holds logits for edges j = q + 4*jj (its own head h);
// max/sum folded over the 4-lane head group via shfl_xor 1,2.
// Weights broadcast by one shuffle per edge during accumulation.
// Gather is software-pipelined depth 4 (8 loads in flight) and issued
// BEFORE the scattered g_el logit loads, overlapping their latency.
// ---------------------------------------------------------------------------
__global__ __launch_bounds__(256) void gat_aggregate(
        const float* __restrict__ feat,
        const float* __restrict__ bias,
        const int*   __restrict__ src,
        float* __restrict__ out) {
    const int t    = threadIdx.x;
    const int warp = t >> 5;
    const int lane = t & 31;
    const int n    = blockIdx.x * 8 + warp;

    const int h    = lane >> 2;          // head 0..7
    const int q    = lane & 3;           // quarter 0..3
    const int off0 = h * D + q * 8;      // first float4
    // second float4 at off0 + 4

    // ---- src indices (uniform 64B region, L1 broadcast) -------------------
    int sj[DEG];
    {
        const int4* sp = reinterpret_cast<const int4*>(src + n * DEG);
#pragma unroll
        for (int p = 0; p < 4; p++) {
            int4 v4 = sp[p];
            sj[4 * p + 0] = v4.x; sj[4 * p + 1] = v4.y;
            sj[4 * p + 2] = v4.z; sj[4 * p + 3] = v4.w;
        }
    }

    // ---- prefetch first 4 edges (issued before logit loads) ---------------
    float4 pv0[4], pv1[4];
#pragma unroll
    for (int p = 0; p < 4; p++) {
        const float* b = feat + (size_t)sj[p] * HD + off0;
        pv0[p] = *reinterpret_cast<const float4*>(b);
        pv1[p] = *reinterpret_cast<const float4*>(b + 4);
    }

    // ---- logits for edges j = q + 4*jj, this lane's head h ----------------
    const float er = g_er[n * H + h];
    float a[4];
    {
        float e[4];
#pragma unroll
        for (int jj = 0; jj < 4; jj++) {
            float v = g_el[sj[q + 4 * jj] * H + h] + er;
            e[jj] = (v > 0.f) ? v : 0.2f * v;
        }
        float m = fmaxf(fmaxf(e[0], e[1]), fmaxf(e[2], e[3]));
        m = fmaxf(m, __shfl_xor_sync(0xffffffffu, m, 1));
        m = fmaxf(m, __shfl_xor_sync(0xffffffffu, m, 2));

        float s = 0.f;
#pragma unroll
        for (int jj = 0; jj < 4; jj++) {
            a[jj] = __expf(e[jj] - m);
            s += a[jj];
        }
        s += __shfl_xor_sync(0xffffffffu, s, 1);
        s += __shfl_xor_sync(0xffffffffu, s, 2);
        const float inv = 1.f / s;
#pragma unroll
        for (int jj = 0; jj < 4; jj++) a[jj] *= inv;
    }

    // ---- pipelined weighted accumulate -------------------------------------
    float4 acc0 = *reinterpret_cast<const float4*>(bias + off0);
    float4 acc1 = *reinterpret_cast<const float4*>(bias + off0 + 4);

    const int srcl = (lane & ~3);   // base lane of this head group
#pragma unroll
    for (int j = 0; j < DEG; j++) {
        const float4 c0 = pv0[j & 3];
        const float4 c1 = pv1[j & 3];
        if (j < DEG - 4) {
            const float* b = feat + (size_t)sj[j + 4] * HD + off0;
            pv0[j & 3] = *reinterpret_cast<const float4*>(b);
            pv1[j & 3] = *reinterpret_cast<const float4*>(b + 4);
        }
        // owner of edge j's weight within this head group: lane srcl|(j&3),
        // stored in its a[j>>2]
        const float aj = __shfl_sync(0xffffffffu, a[j >> 2], srcl | (j & 3));
        acc0.x += aj * c0.x;  acc0.y += aj * c0.y;
        acc0.z += aj * c0.z;  acc0.w += aj * c0.w;
        acc1.x += aj * c1.x;  acc1.y += aj * c1.y;
        acc1.z += aj * c1.z;  acc1.w += aj * c1.w;
    }

    float* o = out + (size_t)n * HD + off0;
    *reinterpret_cast<float4*>(o)     = acc0;
    *reinterpret_cast<float4*>(o + 4) = acc1;
}

// ---------------------------------------------------------------------------
extern "C" void kernel_launch(void* const* d_in, const int* in_sizes, int n_in,
                              void* d_out, int out_size) {
    const float* feat   = (const float*)d_in[0];
    const float* attn_l = (const float*)d_in[1];
    const float* attn_r = (const float*)d_in[2];
    const float* bias   = (const float*)d_in[3];
    const int*   src    = (const int*)d_in[4];
    // d_in[5] = dst: structurally repeat(arange(N), DEG); not needed.

    float* out = (float*)d_out;

    int blocks1 = (N_NODES + 7) / 8;
    precompute_dots<<<blocks1, 256>>>(feat, attn_l, attn_r);

    // one warp per node, 8 nodes per 256-thread block; 50000/8 = 6250
    gat_aggregate<<<N_NODES / 8, 256>>>(feat, bias, src, out);
}

// round 6
// speedup vs baseline: 1.1811x; 1.1811x over previous
#include <cuda_runtime.h>
#include <math.h>

#define N_NODES 50000
#define H 8
#define D 32
#define DEG 16
#define HD (H * D)            // 256
#define NH (N_NODES * H)

// Scratch for precomputed attention dot-products (no cudaMalloc allowed).
__device__ float g_el[NH];
__device__ float g_er[NH];

__device__ __forceinline__ float dot4(float4 a, float4 b) {
    return a.x * b.x + a.y * b.y + a.z * b.z + a.w * b.w;
}

// ---------------------------------------------------------------------------
// Kernel 1: one warp per node, fully coalesced (unchanged, ~9us).
// ---------------------------------------------------------------------------
__global__ __launch_bounds__(256) void precompute_dots(
        const float* __restrict__ feat,
        const float* __restrict__ attn_l,
        const float* __restrict__ attn_r) {
    const int gw   = (blockIdx.x * blockDim.x + threadIdx.x) >> 5;  // node
    const int lane = threadIdx.x & 31;
    if (gw >= N_NODES) return;

    const float4* f4 = reinterpret_cast<const float4*>(feat) + (size_t)gw * 64;
    const float4* al = reinterpret_cast<const float4*>(attn_l);
    const float4* ar = reinterpret_cast<const float4*>(attn_r);

    const float4 f0 = f4[lane];
    const float4 f1 = f4[lane + 32];
    const float4 a0 = al[lane], a1 = al[lane + 32];
    const float4 b0 = ar[lane], b1 = ar[lane + 32];

    float pl0 = dot4(f0, a0);
    float pl1 = dot4(f1, a1);
    float pr0 = dot4(f0, b0);
    float pr1 = dot4(f1, b1);

#pragma unroll
    for (int m = 4; m >= 1; m >>= 1) {
        pl0 += __shfl_xor_sync(0xffffffffu, pl0, m);
        pl1 += __shfl_xor_sync(0xffffffffu, pl1, m);
        pr0 += __shfl_xor_sync(0xffffffffu, pr0, m);
        pr1 += __shfl_xor_sync(0xffffffffu, pr1, m);
    }

    const int g    = lane >> 3;
    const int lo   = lane & 7;
    const int base = gw * H;
    if      (lo == 0) g_el[base + g]     = pl0;
    else if (lo == 1) g_el[base + g + 4] = pl1;
    else if (lo == 2) g_er[base + g]     = pr0;
    else if (lo == 3) g_er[base + g + 4] = pr1;
}

// ---------------------------------------------------------------------------
// Kernel 2: one warp per node, barrier-free, COALESCED layout.
// Lane l owns float4 #l (floats l*4..l*4+3, heads 0-3 => head g=l>>3)
// and float4 #(l+32) (floats 128+l*4.., heads 4-7 => head g+4).
// Each LDG.128 is a 512B-contiguous warp transaction: 8 wavefronts per
// edge-KB (optimal), vs 16 in the round-5 layout.
//
// Logits: lane (g, lo3=l&7) computes logits of edges lo3, lo3+8 for BOTH
// heads g and g+4; softmax folded over the 8-lane group (xor 4,2,1).
// Weights published via padded smem + __syncwarp (broadcast reads,
// conflict-free). Gather software-pipelined depth 4, issued before the
// scattered logit loads. No __syncthreads anywhere.
// ---------------------------------------------------------------------------
__global__ __launch_bounds__(256) void gat_aggregate(
        const float* __restrict__ feat,
        const float* __restrict__ bias,
        const int*   __restrict__ src,
        float* __restrict__ out) {
    const int t    = threadIdx.x;
    const int warp = t >> 5;
    const int lane = t & 31;
    const int n    = blockIdx.x * 8 + warp;

    const int g    = lane >> 3;          // lane group 0..3 -> heads g, g+4
    const int lo3  = lane & 7;

    // padded to 17 so the 4 distinct broadcast addresses per LDS are
    // conflict-free across lane groups
    __shared__ float s_w[8][H][17];

    // ---- src indices (uniform 64B region, L1 broadcast) -------------------
    int sj[DEG];
    {
        const int4* sp = reinterpret_cast<const int4*>(src + n * DEG);
#pragma unroll
        for (int p = 0; p < 4; p++) {
            int4 v4 = sp[p];
            sj[4 * p + 0] = v4.x; sj[4 * p + 1] = v4.y;
            sj[4 * p + 2] = v4.z; sj[4 * p + 3] = v4.w;
        }
    }

    // ---- prefetch first 4 edges (2x contiguous 512B per edge) -------------
    float4 pv0[4], pv1[4];
#pragma unroll
    for (int p = 0; p < 4; p++) {
        const float4* b = reinterpret_cast<const float4*>(
            feat + (size_t)sj[p] * HD);
        pv0[p] = b[lane];
        pv1[p] = b[lane + 32];
    }

    // ---- logits for edges lo3, lo3+8; heads g and g+4 ----------------------
    {
        const int s0 = sj[lo3];
        const int s1 = sj[lo3 + 8];
        const float er0 = g_er[n * H + g];
        const float er1 = g_er[n * H + g + 4];

        float e00 = g_el[s0 * H + g]     + er0;   // head g,  edge lo3
        float e01 = g_el[s1 * H + g]     + er0;   // head g,  edge lo3+8
        float e10 = g_el[s0 * H + g + 4] + er1;   // head g+4, edge lo3
        float e11 = g_el[s1 * H + g + 4] + er1;   // head g+4, edge lo3+8
        e00 = (e00 > 0.f) ? e00 : 0.2f * e00;
        e01 = (e01 > 0.f) ? e01 : 0.2f * e01;
        e10 = (e10 > 0.f) ? e10 : 0.2f * e10;
        e11 = (e11 > 0.f) ? e11 : 0.2f * e11;

        float m0 = fmaxf(e00, e01);
        float m1 = fmaxf(e10, e11);
#pragma unroll
        for (int msk = 4; msk >= 1; msk >>= 1) {
            m0 = fmaxf(m0, __shfl_xor_sync(0xffffffffu, m0, msk));
            m1 = fmaxf(m1, __shfl_xor_sync(0xffffffffu, m1, msk));
        }

        float x00 = __expf(e00 - m0), x01 = __expf(e01 - m0);
        float x10 = __expf(e10 - m1), x11 = __expf(e11 - m1);
        float s0s = x00 + x01;
        float s1s = x10 + x11;
#pragma unroll
        for (int msk = 4; msk >= 1; msk >>= 1) {
            s0s += __shfl_xor_sync(0xffffffffu, s0s, msk);
            s1s += __shfl_xor_sync(0xffffffffu, s1s, msk);
        }
        const float i0 = 1.f / s0s;
        const float i1 = 1.f / s1s;

        s_w[warp][g][lo3]         = x00 * i0;
        s_w[warp][g][lo3 + 8]     = x01 * i0;
        s_w[warp][g + 4][lo3]     = x10 * i1;
        s_w[warp][g + 4][lo3 + 8] = x11 * i1;
    }
    __syncwarp();

    // ---- pipelined weighted accumulate -------------------------------------
    float4 acc0, acc1;
    {
        const float4* b4 = reinterpret_cast<const float4*>(bias);
        acc0 = b4[lane];
        acc1 = b4[lane + 32];
    }

    const float* w0 = s_w[warp][g];       // weights for head g
    const float* w1 = s_w[warp][g + 4];   // weights for head g+4

#pragma unroll
    for (int j = 0; j < DEG; j++) {
        const float4 c0 = pv0[j & 3];
        const float4 c1 = pv1[j & 3];
        if (j < DEG - 4) {
            const float4* b = reinterpret_cast<const float4*>(
                feat + (size_t)sj[j + 4] * HD);
            pv0[j & 3] = b[lane];
            pv1[j & 3] = b[lane + 32];
        }
        const float a0 = w0[j];
        const float a1 = w1[j];
        acc0.x += a0 * c0.x;  acc0.y += a0 * c0.y;
        acc0.z += a0 * c0.z;  acc0.w += a0 * c0.w;
        acc1.x += a1 * c1.x;  acc1.y += a1 * c1.y;
        acc1.z += a1 * c1.z;  acc1.w += a1 * c1.w;
    }

    float4* o4 = reinterpret_cast<float4*>(out + (size_t)n * HD);
    o4[lane]      = acc0;
    o4[lane + 32] = acc1;
}

// ---------------------------------------------------------------------------
extern "C" void kernel_launch(void* const* d_in, const int* in_sizes, int n_in,
                              void* d_out, int out_size) {
    const float* feat   = (const float*)d_in[0];
    const float* attn_l = (const float*)d_in[1];
    const float* attn_r = (const float*)d_in[2];
    const float* bias   = (const float*)d_in[3];
    const int*   src    = (const int*)d_in[4];
    // d_in[5] = dst: structurally repeat(arange(N), DEG); not needed.

    float* out = (float*)d_out;

    int blocks1 = (N_NODES + 7) / 8;
    precompute_dots<<<blocks1, 256>>>(feat, attn_l, attn_r);

    // one warp per node, 8 nodes per 256-thread block
    gat_aggregate<<<N_NODES / 8, 256>>>(feat, bias, src, out);
}

// round 7
// speedup vs baseline: 1.2496x; 1.0580x over previous
#include <cuda_runtime.h>
#include <math.h>

#define N_NODES 50000
#define H 8
#define D 32
#define DEG 16
#define HD (H * D)            // 256
#define NH (N_NODES * H)

// Scratch for precomputed attention dot-products (no cudaMalloc allowed).
__device__ float g_el[NH];
__device__ float g_er[NH];

__device__ __forceinline__ float dot4(float4 a, float4 b) {
    return a.x * b.x + a.y * b.y + a.z * b.z + a.w * b.w;
}

// ---------------------------------------------------------------------------
// Kernel 1: one warp per node, fully coalesced (unchanged, ~9us).
// ---------------------------------------------------------------------------
__global__ __launch_bounds__(256) void precompute_dots(
        const float* __restrict__ feat,
        const float* __restrict__ attn_l,
        const float* __restrict__ attn_r) {
    const int gw   = (blockIdx.x * blockDim.x + threadIdx.x) >> 5;  // node
    const int lane = threadIdx.x & 31;
    if (gw >= N_NODES) return;

    const float4* f4 = reinterpret_cast<const float4*>(feat) + (size_t)gw * 64;
    const float4* al = reinterpret_cast<const float4*>(attn_l);
    const float4* ar = reinterpret_cast<const float4*>(attn_r);

    const float4 f0 = f4[lane];
    const float4 f1 = f4[lane + 32];
    const float4 a0 = al[lane], a1 = al[lane + 32];
    const float4 b0 = ar[lane], b1 = ar[lane + 32];

    float pl0 = dot4(f0, a0);
    float pl1 = dot4(f1, a1);
    float pr0 = dot4(f0, b0);
    float pr1 = dot4(f1, b1);

#pragma unroll
    for (int m = 4; m >= 1; m >>= 1) {
        pl0 += __shfl_xor_sync(0xffffffffu, pl0, m);
        pl1 += __shfl_xor_sync(0xffffffffu, pl1, m);
        pr0 += __shfl_xor_sync(0xffffffffu, pr0, m);
        pr1 += __shfl_xor_sync(0xffffffffu, pr1, m);
    }

    const int g    = lane >> 3;
    const int lo   = lane & 7;
    const int base = gw * H;
    if      (lo == 0) g_el[base + g]     = pl0;
    else if (lo == 1) g_el[base + g + 4] = pl1;
    else if (lo == 2) g_er[base + g]     = pr0;
    else if (lo == 3) g_er[base + g + 4] = pr1;
}

// ---------------------------------------------------------------------------
// Kernel 2: one warp per node, barrier-free, coalesced layout (round-6
// structure) with register pressure cut for occupancy:
//   - src ids live in per-warp smem (LDS reads), not 16 registers
//   - __launch_bounds__(256, 4) caps regs at 64/thread
// Lane l owns float4 #l (heads 0-3, head g=l>>3) and #(l+32) (heads 4-7).
// Each LDG.128 is a 512B-contiguous warp transaction. Gather pipelined
// depth 4, issued before the scattered logit loads. No __syncthreads.
// ---------------------------------------------------------------------------
__global__ __launch_bounds__(256, 4) void gat_aggregate(
        const float* __restrict__ feat,
        const float* __restrict__ bias,
        const int*   __restrict__ src,
        float* __restrict__ out) {
    const int t    = threadIdx.x;
    const int warp = t >> 5;
    const int lane = t & 31;
    const int n    = blockIdx.x * 8 + warp;

    const int g    = lane >> 3;          // lane group 0..3 -> heads g, g+4
    const int lo3  = lane & 7;

    __shared__ int   s_src[8][DEG];
    // padded to 17 so broadcast reads are conflict-free across lane groups
    __shared__ float s_w[8][H][17];

    // ---- src indices into per-warp smem ------------------------------------
    if (lane < DEG) s_src[warp][lane] = src[n * DEG + lane];
    __syncwarp();

    const int* sjp = s_src[warp];

    // ---- prefetch first 4 edges (2x contiguous 512B per edge) -------------
    float4 pv0[4], pv1[4];
#pragma unroll
    for (int p = 0; p < 4; p++) {
        const float4* b = reinterpret_cast<const float4*>(
            feat + (size_t)sjp[p] * HD);
        pv0[p] = b[lane];
        pv1[p] = b[lane + 32];
    }

    // ---- logits for edges lo3, lo3+8; heads g and g+4 ----------------------
    {
        const int s0 = sjp[lo3];
        const int s1 = sjp[lo3 + 8];
        const float er0 = g_er[n * H + g];
        const float er1 = g_er[n * H + g + 4];

        float e00 = g_el[s0 * H + g]     + er0;
        float e01 = g_el[s1 * H + g]     + er0;
        float e10 = g_el[s0 * H + g + 4] + er1;
        float e11 = g_el[s1 * H + g + 4] + er1;
        e00 = (e00 > 0.f) ? e00 : 0.2f * e00;
        e01 = (e01 > 0.f) ? e01 : 0.2f * e01;
        e10 = (e10 > 0.f) ? e10 : 0.2f * e10;
        e11 = (e11 > 0.f) ? e11 : 0.2f * e11;

        float m0 = fmaxf(e00, e01);
        float m1 = fmaxf(e10, e11);
#pragma unroll
        for (int msk = 4; msk >= 1; msk >>= 1) {
            m0 = fmaxf(m0, __shfl_xor_sync(0xffffffffu, m0, msk));
            m1 = fmaxf(m1, __shfl_xor_sync(0xffffffffu, m1, msk));
        }

        float x00 = __expf(e00 - m0), x01 = __expf(e01 - m0);
        float x10 = __expf(e10 - m1), x11 = __expf(e11 - m1);
        float s0s = x00 + x01;
        float s1s = x10 + x11;
#pragma unroll
        for (int msk = 4; msk >= 1; msk >>= 1) {
            s0s += __shfl_xor_sync(0xffffffffu, s0s, msk);
            s1s += __shfl_xor_sync(0xffffffffu, s1s, msk);
        }
        const float i0 = 1.f / s0s;
        const float i1 = 1.f / s1s;

        s_w[warp][g][lo3]         = x00 * i0;
        s_w[warp][g][lo3 + 8]     = x01 * i0;
        s_w[warp][g + 4][lo3]     = x10 * i1;
        s_w[warp][g + 4][lo3 + 8] = x11 * i1;
    }
    __syncwarp();

    // ---- pipelined weighted accumulate -------------------------------------
    float4 acc0, acc1;
    {
        const float4* b4 = reinterpret_cast<const float4*>(bias);
        acc0 = b4[lane];
        acc1 = b4[lane + 32];
    }

    const float* w0 = s_w[warp][g];       // weights for head g
    const float* w1 = s_w[warp][g + 4];   // weights for head g+4

#pragma unroll
    for (int j = 0; j < DEG; j++) {
        const float4 c0 = pv0[j & 3];
        const float4 c1 = pv1[j & 3];
        if (j < DEG - 4) {
            const float4* b = reinterpret_cast<const float4*>(
                feat + (size_t)sjp[j + 4] * HD);
            pv0[j & 3] = b[lane];
            pv1[j & 3] = b[lane + 32];
        }
        const float a0 = w0[j];
        const float a1 = w1[j];
        acc0.x += a0 * c0.x;  acc0.y += a0 * c0.y;
        acc0.z += a0 * c0.z;  acc0.w += a0 * c0.w;
        acc1.x += a1 * c1.x;  acc1.y += a1 * c1.y;
        acc1.z += a1 * c1.z;  acc1.w += a1 * c1.w;
    }

    float4* o4 = reinterpret_cast<float4*>(out + (size_t)n * HD);
    o4[lane]      = acc0;
    o4[lane + 32] = acc1;
}

// ---------------------------------------------------------------------------
extern "C" void kernel_launch(void* const* d_in, const int* in_sizes, int n_in,
                              void* d_out, int out_size) {
    const float* feat   = (const float*)d_in[0];
    const float* attn_l = (const float*)d_in[1];
    const float* attn_r = (const float*)d_in[2];
    const float* bias   = (const float*)d_in[3];
    const int*   src    = (const int*)d_in[4];
    // d_in[5] = dst: structurally repeat(arange(N), DEG); not needed.

    float* out = (float*)d_out;

    int blocks1 = (N_NODES + 7) / 8;
    precompute_dots<<<blocks1, 256>>>(feat, attn_l, attn_r);

    // one warp per node, 8 nodes per 256-thread block
    gat_aggregate<<<N_NODES / 8, 256>>>(feat, bias, src, out);
}